// round 7
// baseline (speedup 1.0000x reference)
#include <cuda_runtime.h>
#include <cuda_bf16.h>

// Problem constants (B=8, N=256, H=128)
#define BB 8
#define NN 256
#define HH 128
#define ROWS (BB * NN)        // 2048
#define TI 16                 // i-rows per edge CTA
#define TJ 32                 // j-tile per edge CTA
#define NSPLIT 8              // j-range split (inner range == TJ)

typedef unsigned long long ull;

// Scratch (allocation-free rule: __device__ globals)
// g_P = 0.5*(node@We1a + be1); g_Q = 0.5*(node@We1b)  (pre-halved for tanh-silu)
__device__ float g_P[ROWS * HH];
__device__ float g_Q[ROWS * HH];
__device__ float g_S[NSPLIT][ROWS * HH];

// ---------------- packed f32x2 + MUFU helpers ----------------
__device__ __forceinline__ ull fma2(ull a, ull b, ull c) {
    ull d; asm("fma.rn.f32x2 %0, %1, %2, %3;" : "=l"(d) : "l"(a), "l"(b), "l"(c)); return d;
}
__device__ __forceinline__ ull add2(ull a, ull b) {
    ull d; asm("add.rn.f32x2 %0, %1, %2;" : "=l"(d) : "l"(a), "l"(b)); return d;
}
__device__ __forceinline__ ull mul2(ull a, ull b) {
    ull d; asm("mul.rn.f32x2 %0, %1, %2;" : "=l"(d) : "l"(a), "l"(b)); return d;
}
__device__ __forceinline__ ull pack2(float lo, float hi) {
    ull d; asm("mov.b64 %0, {%1, %2};" : "=l"(d) : "f"(lo), "f"(hi)); return d;
}
__device__ __forceinline__ void unpack2(ull v, float& lo, float& hi) {
    asm("mov.b64 {%0, %1}, %2;" : "=f"(lo), "=f"(hi) : "l"(v));
}
__device__ __forceinline__ float tanhfast(float x) {
    float y; asm("tanh.approx.f32 %0, %1;" : "=f"(y) : "f"(x)); return y;
}
__device__ __forceinline__ float sqrtfast(float x) {
    float y; asm("sqrt.approx.f32 %0, %1;" : "=f"(y) : "f"(x)); return y;
}
__device__ __forceinline__ float fast_sigmoid(float x) {
    float e; asm("ex2.approx.f32 %0, %1;" : "=f"(e) : "f"(-1.4426950408889634f * x));
    float r; asm("rcp.approx.f32 %0, %1;" : "=f"(r) : "f"(1.0f + e));
    return r;
}

// No-op kernel: shifts ncu's fixed profile slot so k_edge gets profiled.
__global__ void k_nop() {}

// ---------------------------------------------------------------------------
// Kernel 1: P' = 0.5*(node@We1a + be1) ; Q' = 0.5*(node@We1b)
// 16 rows/CTA, 512 threads, grid 128. Weights staged to smem in 16-e chunks
// (both halves), double-buffered; FMA loop fed entirely from LDS.
// tid bits: [0:7)=k, bit7=half(P/Q), bit8=row-pair-group (4 pairs each).
// ---------------------------------------------------------------------------
__global__ __launch_bounds__(512, 1)
void k_pq(const float* __restrict__ node,
          const float* __restrict__ We1,
          const float* __restrict__ be1) {
    __shared__ __align__(16) ull xs2[HH][8];           // 8 KB: (x[2rp][e], x[2rp+1][e])
    __shared__ __align__(16) float wbuf[2][2][16][HH]; // 32 KB: [buf][half][e][k]

    int row0 = blockIdx.x * 16;
    int tid = threadIdx.x;
    int k = tid & 127;
    int half = (tid >> 7) & 1;
    int rp0 = (tid >> 8) * 4;

    {
        int rp = tid >> 6;            // 0..7
        int e0 = (tid & 63) * 2;      // 0..126
        float2 a = *(const float2*)&node[(row0 + 2 * rp) * HH + e0];
        float2 b = *(const float2*)&node[(row0 + 2 * rp + 1) * HH + e0];
        xs2[e0][rp] = pack2(a.x, b.x);
        xs2[e0 + 1][rp] = pack2(a.y, b.y);
    }
    // stage chunk 0: halves h=0,1; chunk = 16 e-rows x 128 k = 512 float4/half
    {
        int h = tid >> 8;             // use tid/256 as half selector: 2 float4 each
        int w = tid & 255;
        const float4* src = (const float4*)(We1 + h * HH * HH);
        float4* dst = (float4*)wbuf[0][h];
        dst[w] = src[w];
        dst[w + 256] = src[w + 256];
    }
    __syncthreads();

    float bv = half ? 0.0f : be1[k];
    ull acc2[4];
#pragma unroll
    for (int p = 0; p < 4; p++) acc2[p] = pack2(bv, bv);

    int lh = tid >> 8;                // loader half
    int lw = tid & 255;
    const float4* lsrc = (const float4*)(We1 + lh * HH * HH);

#pragma unroll
    for (int c = 0; c < 8; c++) {
        float4 pf0, pf1;
        if (c < 7) {                  // issue prefetch LDGs early
            pf0 = lsrc[(c + 1) * 512 + lw];
            pf1 = lsrc[(c + 1) * 512 + lw + 256];
        }
        const float (*wc)[HH] = wbuf[c & 1][half];
#pragma unroll
        for (int e = 0; e < 16; e++) {
            float w = wc[e][k];
            ull w2 = pack2(w, w);
            ulonglong2 xa = *(const ulonglong2*)&xs2[c * 16 + e][rp0];
            ulonglong2 xb = *(const ulonglong2*)&xs2[c * 16 + e][rp0 + 2];
            acc2[0] = fma2(xa.x, w2, acc2[0]);
            acc2[1] = fma2(xa.y, w2, acc2[1]);
            acc2[2] = fma2(xb.x, w2, acc2[2]);
            acc2[3] = fma2(xb.y, w2, acc2[3]);
        }
        if (c < 7) {
            float4* dst = (float4*)wbuf[(c + 1) & 1][lh];
            dst[lw] = pf0;
            dst[lw + 256] = pf1;
        }
        __syncthreads();
    }

    float* dst = half ? g_Q : g_P;
    ull h2c = pack2(0.5f, 0.5f);
#pragma unroll
    for (int p = 0; p < 4; p++) {
        acc2[p] = mul2(acc2[p], h2c);
        float lo, hi; unpack2(acc2[p], lo, hi);
        int rp = rp0 + p;
        dst[(row0 + 2 * rp) * HH + k] = lo;
        dst[(row0 + 2 * rp + 1) * HH + k] = hi;
    }
}

// ---------------------------------------------------------------------------
// Kernel 2 (R5 form): S[b,i,k] += mj * silu(h),  h/2 = P'_i + Q'_j + dist*wd'
// silu(h) = (h/2)*(1 + tanh(h/2)) with f32 tanh. dist precomputed to smem.
// grid (8, N/TI, B) = 1024 CTAs, 256 threads, single prologue sync.
// ---------------------------------------------------------------------------
__global__ __launch_bounds__(256)
void k_edge(const float* __restrict__ pos,
            const float* __restrict__ mask,
            const float* __restrict__ We1) {
    __shared__ __align__(16) float qsm[TJ][HH];   // 16 KB
    __shared__ __align__(16) float bsm[TI][HH];   // 8 KB
    __shared__ float dsm[TI][TJ];                 // 2 KB
    __shared__ float msm[TJ];

    int js = blockIdx.x;
    int i0 = blockIdx.y * TI;
    int b  = blockIdx.z;
    int tid = threadIdx.x;
    int j0 = js * TJ;

#pragma unroll
    for (int q = 0; q < 8; q++) {
        int idx = tid + q * 256;
        bsm[idx >> 7][idx & 127] = g_P[(b * NN + i0 + (idx >> 7)) * HH + (idx & 127)];
    }
    {
        const float4* qsrc = (const float4*)&g_Q[(b * NN + j0) * HH];
#pragma unroll
        for (int q = 0; q < 4; q++)
            ((float4*)qsm)[tid + q * 256] = qsrc[tid + q * 256];
    }
    if (tid < TJ) msm[tid] = mask[b * NN + j0 + tid];
#pragma unroll
    for (int t = 0; t < 2; t++) {
        int idx = tid + t * 256;
        int il = idx >> 5, jl = idx & 31;
        const float* pi = &pos[(b * NN + i0 + il) * 3];
        const float* pj = &pos[(b * NN + j0 + jl) * 3];
        float dx = pi[0] - pj[0], dy = pi[1] - pj[1], dz = pi[2] - pj[2];
        float sq = fmaf(dx, dx, fmaf(dy, dy, dz * dz));
        dsm[il][jl] = (sq > 0.0f) ? sqrtfast(sq) : 0.0f;
    }
    __syncthreads();

    int il = tid >> 4;
    int k0 = (tid & 15) * 8;

    ull base2[4], wd2[4], acc2[4];
#pragma unroll
    for (int p = 0; p < 4; p++) {
        float wlo = 0.5f * We1[2 * HH * HH + k0 + 2 * p];
        float whi = 0.5f * We1[2 * HH * HH + k0 + 2 * p + 1];
        wd2[p] = pack2(wlo, whi);
        base2[p] = ((const ull*)&bsm[il][k0])[p];
        acc2[p] = 0ULL;
    }

#pragma unroll 4
    for (int jl = 0; jl < TJ; jl++) {
        float dist = dsm[il][jl];
        float mj = msm[jl];
        ull dist2 = pack2(dist, dist);
        ull mj2 = pack2(mj, mj);
        ulonglong2 qa = *(const ulonglong2*)&qsm[jl][k0];
        ulonglong2 qb = *(const ulonglong2*)&qsm[jl][k0 + 4];
        ull qv[4] = {qa.x, qa.y, qb.x, qb.y};
#pragma unroll
        for (int p = 0; p < 4; p++) {
            ull h2 = fma2(dist2, wd2[p], add2(base2[p], qv[p]));  // h/2
            float hl, hh; unpack2(h2, hl, hh);
            ull t2 = pack2(tanhfast(hl), tanhfast(hh));
            ull s2 = fma2(h2, t2, h2);        // silu(h) = h2*(1+t)
            acc2[p] = fma2(mj2, s2, acc2[p]); // += mj * silu
        }
    }
    float* dst = &g_S[js][(b * NN + i0 + il) * HH + k0];
#pragma unroll
    for (int p = 0; p < 4; p++) {
        float lo, hi; unpack2(acc2[p], lo, hi);
        dst[2 * p] = lo;
        dst[2 * p + 1] = hi;
    }
}

// ---------------------------------------------------------------------------
// Kernel 3: agg -> node MLP -> residual.  16 rows/CTA, 512 threads, grid 128.
// All weight matrices staged to smem in 32-e chunks; FMA loops LDS-fed.
// tid bits: [0:7)=k, [7:9)=row-quarter (4 rows each).
// ---------------------------------------------------------------------------
__global__ __launch_bounds__(512, 1)
void k_final(const float* __restrict__ node,
             const float* __restrict__ mask,
             const float* __restrict__ We2,
             const float* __restrict__ be2,
             const float* __restrict__ Wn1,
             const float* __restrict__ bn1,
             const float* __restrict__ Wn2,
             const float* __restrict__ bn2,
             float* __restrict__ out) {
    __shared__ __align__(16) float wsm[32][HH];     // 16 KB weight chunk
    __shared__ __align__(16) float XA[16][2 * HH];  // 16 KB [X | A]
    __shared__ __align__(16) float SU[16][HH];      // 8 KB: S (stage A), then U (B/C)
    __shared__ float msk[16];
    __shared__ float cntsh;

    int row0 = blockIdx.x * 16;
    int b = row0 >> 8;
    int tid = threadIdx.x;
    int k = tid & 127;
    int rb = (tid >> 7) * 4;

#pragma unroll
    for (int q = 0; q < 4; q++) {
        int r = rb + q;
        int g = (row0 + r) * HH + k;
        XA[r][k] = node[g];
        float s = 0.0f;
#pragma unroll
        for (int t = 0; t < NSPLIT; t++) s += g_S[t][g];
        SU[r][k] = s;
    }
    if (tid < 16) msk[tid] = mask[row0 + tid];
    if (tid < 32) {
        float c = 0.0f;
#pragma unroll
        for (int m = 0; m < 8; m++) c += mask[b * NN + tid * 8 + m];
#pragma unroll
        for (int o = 16; o; o >>= 1) c += __shfl_xor_sync(0xffffffffu, c, o);
        if (tid == 0) cntsh = c;
    }
    __syncthreads();
    float cnt = cntsh;

    // Stage A: agg = msk*(S@We2 + cnt*be2)/max(msk*cnt,1) -> XA[:, HH+k]
    {
        float acc[4] = {0.f, 0.f, 0.f, 0.f};
        const float4* W4 = (const float4*)We2;
#pragma unroll
        for (int c = 0; c < 4; c++) {
            ((float4*)wsm)[tid] = W4[c * 1024 + tid];
            ((float4*)wsm)[tid + 512] = W4[c * 1024 + tid + 512];
            __syncthreads();
#pragma unroll
            for (int g = 0; g < 8; g++) {
                float w[4];
#pragma unroll
                for (int e = 0; e < 4; e++) w[e] = wsm[g * 4 + e][k];
#pragma unroll
                for (int q = 0; q < 4; q++) {
                    float4 s = *(const float4*)&SU[rb + q][c * 32 + g * 4];
                    acc[q] = fmaf(s.x, w[0], acc[q]);
                    acc[q] = fmaf(s.y, w[1], acc[q]);
                    acc[q] = fmaf(s.z, w[2], acc[q]);
                    acc[q] = fmaf(s.w, w[3], acc[q]);
                }
            }
            __syncthreads();
        }
        float be2k = be2[k];
#pragma unroll
        for (int q = 0; q < 4; q++) {
            int r = rb + q;
            float denom = fmaxf(msk[r] * cnt, 1.0f);
            XA[r][HH + k] = msk[r] * (acc[q] + cnt * be2k) * (1.0f / denom);
        }
        __syncthreads();
    }

    // Stage B: u1 = silu(XA @ Wn1 + bn1) -> SU
    {
        float b1 = bn1[k];
        float acc[4] = {b1, b1, b1, b1};
        const float4* W4 = (const float4*)Wn1;
#pragma unroll
        for (int c = 0; c < 8; c++) {
            ((float4*)wsm)[tid] = W4[c * 1024 + tid];
            ((float4*)wsm)[tid + 512] = W4[c * 1024 + tid + 512];
            __syncthreads();
#pragma unroll
            for (int g = 0; g < 8; g++) {
                float w[4];
#pragma unroll
                for (int e = 0; e < 4; e++) w[e] = wsm[g * 4 + e][k];
#pragma unroll
                for (int q = 0; q < 4; q++) {
                    float4 x = *(const float4*)&XA[rb + q][c * 32 + g * 4];
                    acc[q] = fmaf(x.x, w[0], acc[q]);
                    acc[q] = fmaf(x.y, w[1], acc[q]);
                    acc[q] = fmaf(x.z, w[2], acc[q]);
                    acc[q] = fmaf(x.w, w[3], acc[q]);
                }
            }
            __syncthreads();
        }
#pragma unroll
        for (int q = 0; q < 4; q++) {
            float h = acc[q];
            SU[rb + q][k] = h * fast_sigmoid(h);
        }
        __syncthreads();
    }

    // Stage C: out = node + msk * (u1 @ Wn2 + bn2)
    {
        float b2 = bn2[k];
        float acc[4] = {b2, b2, b2, b2};
        const float4* W4 = (const float4*)Wn2;
#pragma unroll
        for (int c = 0; c < 4; c++) {
            ((float4*)wsm)[tid] = W4[c * 1024 + tid];
            ((float4*)wsm)[tid + 512] = W4[c * 1024 + tid + 512];
            __syncthreads();
#pragma unroll
            for (int g = 0; g < 8; g++) {
                float w[4];
#pragma unroll
                for (int e = 0; e < 4; e++) w[e] = wsm[g * 4 + e][k];
#pragma unroll
                for (int q = 0; q < 4; q++) {
                    float4 u = *(const float4*)&SU[rb + q][c * 32 + g * 4];
                    acc[q] = fmaf(u.x, w[0], acc[q]);
                    acc[q] = fmaf(u.y, w[1], acc[q]);
                    acc[q] = fmaf(u.z, w[2], acc[q]);
                    acc[q] = fmaf(u.w, w[3], acc[q]);
                }
            }
            __syncthreads();
        }
#pragma unroll
        for (int q = 0; q < 4; q++) {
            int r = rb + q;
            out[(row0 + r) * HH + k] = XA[r][k] + msk[r] * acc[q];
        }
    }
}

extern "C" void kernel_launch(void* const* d_in, const int* in_sizes, int n_in,
                              void* d_out, int out_size) {
    (void)in_sizes; (void)n_in; (void)out_size;
    const float* node = (const float*)d_in[0];
    const float* pos  = (const float*)d_in[1];
    const float* mask = (const float*)d_in[2];
    const float* We1  = (const float*)d_in[3];
    const float* be1  = (const float*)d_in[4];
    const float* We2  = (const float*)d_in[5];
    const float* be2  = (const float*)d_in[6];
    const float* Wn1  = (const float*)d_in[7];
    const float* bn1  = (const float*)d_in[8];
    const float* Wn2  = (const float*)d_in[9];
    const float* bn2  = (const float*)d_in[10];
    float* out = (float*)d_out;

    k_nop<<<1, 32>>>();   // shifts ncu's profile slot onto k_edge
    k_pq<<<ROWS / 16, 512>>>(node, We1, be1);
    k_edge<<<dim3(NSPLIT, NN / TI, BB), 256>>>(pos, mask, We1);
    k_final<<<ROWS / 16, 512>>>(node, mask, We2, be2, Wn1, bn1, Wn2, bn2, out);
}

// round 8
// speedup vs baseline: 1.0888x; 1.0888x over previous
#include <cuda_runtime.h>
#include <cuda_bf16.h>

// Problem constants (B=8, N=256, H=128)
#define BB 8
#define NN 256
#define HH 128
#define ROWS (BB * NN)        // 2048
#define TI 16                 // i-rows per edge CTA
#define TJE 64                // j-range per edge CTA (both tiles resident)
#define NSPLIT 4              // j-range split

typedef unsigned long long ull;

// Scratch (allocation-free rule: __device__ globals)
// g_P = 0.5*(node@We1a + be1); g_Q = 0.5*(node@We1b)  (pre-halved for tanh-silu)
__device__ float g_P[ROWS * HH];
__device__ float g_Q[ROWS * HH];
__device__ float g_S[NSPLIT][ROWS * HH];

// ---------------- packed f32x2 + MUFU helpers ----------------
__device__ __forceinline__ ull fma2(ull a, ull b, ull c) {
    ull d; asm("fma.rn.f32x2 %0, %1, %2, %3;" : "=l"(d) : "l"(a), "l"(b), "l"(c)); return d;
}
__device__ __forceinline__ ull add2(ull a, ull b) {
    ull d; asm("add.rn.f32x2 %0, %1, %2;" : "=l"(d) : "l"(a), "l"(b)); return d;
}
__device__ __forceinline__ ull mul2(ull a, ull b) {
    ull d; asm("mul.rn.f32x2 %0, %1, %2;" : "=l"(d) : "l"(a), "l"(b)); return d;
}
__device__ __forceinline__ ull pack2(float lo, float hi) {
    ull d; asm("mov.b64 %0, {%1, %2};" : "=l"(d) : "f"(lo), "f"(hi)); return d;
}
__device__ __forceinline__ void unpack2(ull v, float& lo, float& hi) {
    asm("mov.b64 {%0, %1}, %2;" : "=f"(lo), "=f"(hi) : "l"(v));
}
__device__ __forceinline__ float tanhfast(float x) {
    float y; asm("tanh.approx.f32 %0, %1;" : "=f"(y) : "f"(x)); return y;
}
__device__ __forceinline__ float sqrtfast(float x) {
    float y; asm("sqrt.approx.f32 %0, %1;" : "=f"(y) : "f"(x)); return y;
}
__device__ __forceinline__ float fast_sigmoid(float x) {
    float e; asm("ex2.approx.f32 %0, %1;" : "=f"(e) : "f"(-1.4426950408889634f * x));
    float r; asm("rcp.approx.f32 %0, %1;" : "=f"(r) : "f"(1.0f + e));
    return r;
}

// ---------------------------------------------------------------------------
// Kernel 1: P' = 0.5*(node@We1a + be1) ; Q' = 0.5*(node@We1b)
// 8 rows/CTA (4 row-pairs), 256 threads, grid 256 (~2 CTAs/SM).
// tid: k = tid&127, half = tid>>7 (P vs Q).
// Row-pairs packed as f32x2; weights reg-double-buffered (16-chunks).
// ---------------------------------------------------------------------------
__global__ __launch_bounds__(256)
void k_pq(const float* __restrict__ node,
          const float* __restrict__ We1,
          const float* __restrict__ be1) {
    __shared__ __align__(16) ull xs2[HH][4];   // 4 KB: xs2[e][p]=(x[2p][e],x[2p+1][e])
    int row0 = blockIdx.x * 8;
    int tid = threadIdx.x;
    int k = tid & 127;
    int half = tid >> 7;

#pragma unroll
    for (int t = 0; t < 2; t++) {
        int idx = tid + t * 256;          // 512 entries
        int e = idx >> 2, p = idx & 3;
        float a = node[(row0 + 2 * p) * HH + e];
        float b = node[(row0 + 2 * p + 1) * HH + e];
        xs2[e][p] = pack2(a, b);
    }
    __syncthreads();

    const float* W = We1 + half * HH * HH + k;
    float bv = half ? 0.0f : be1[k];
    ull acc2[4];
#pragma unroll
    for (int p = 0; p < 4; p++) acc2[p] = pack2(bv, bv);

    float w0[16], w1[16];
#pragma unroll
    for (int e = 0; e < 16; e++) w0[e] = W[e * HH];

#pragma unroll
    for (int c = 0; c < 8; c++) {
        float* wc = (c & 1) ? w1 : w0;
        float* wn = (c & 1) ? w0 : w1;
        if (c < 7) {
#pragma unroll
            for (int e = 0; e < 16; e++) wn[e] = W[((c + 1) * 16 + e) * HH];
        }
#pragma unroll
        for (int e = 0; e < 16; e++) {
            ull w2 = pack2(wc[e], wc[e]);
            ulonglong2 xa = *(const ulonglong2*)&xs2[c * 16 + e][0];
            ulonglong2 xb = *(const ulonglong2*)&xs2[c * 16 + e][2];
            acc2[0] = fma2(xa.x, w2, acc2[0]);
            acc2[1] = fma2(xa.y, w2, acc2[1]);
            acc2[2] = fma2(xb.x, w2, acc2[2]);
            acc2[3] = fma2(xb.y, w2, acc2[3]);
        }
    }
    float* dst = half ? g_Q : g_P;
    ull hc = pack2(0.5f, 0.5f);
#pragma unroll
    for (int p = 0; p < 4; p++) {
        float lo, hi; unpack2(mul2(acc2[p], hc), lo, hi);
        dst[(row0 + 2 * p) * HH + k] = lo;
        dst[(row0 + 2 * p + 1) * HH + k] = hi;
    }
}

// ---------------------------------------------------------------------------
// Kernel 2: S[b,i,k] += mj * silu(h),  h/2 = P'_i + Q'_j + dist*wd'
// silu(h) = (h/2)*(1 + tanh(h/2)), f32 tanh. 64-wide j-range, both tiles
// resident; grid (4, 16, 8) = 512 CTAs, 256 threads, single prologue sync.
// ---------------------------------------------------------------------------
__global__ __launch_bounds__(256)
void k_edge(const float* __restrict__ pos,
            const float* __restrict__ mask,
            const float* __restrict__ We1) {
    __shared__ __align__(16) float qsm[TJE][HH];  // 32 KB
    __shared__ __align__(16) float bsm[TI][HH];   // 8 KB
    __shared__ float dsm[TI][TJE];                // 4 KB
    __shared__ float msm[TJE];

    int js = blockIdx.x;
    int i0 = blockIdx.y * TI;
    int b  = blockIdx.z;
    int tid = threadIdx.x;
    int j0 = js * TJE;

    {
        const float4* bsrc = (const float4*)&g_P[(b * NN + i0) * HH];
#pragma unroll
        for (int q = 0; q < 2; q++)
            ((float4*)bsm)[tid + q * 256] = bsrc[tid + q * 256];
        const float4* qsrc = (const float4*)&g_Q[(b * NN + j0) * HH];
#pragma unroll
        for (int q = 0; q < 8; q++)
            ((float4*)qsm)[tid + q * 256] = qsrc[tid + q * 256];
    }
    if (tid < TJE) msm[tid] = mask[b * NN + j0 + tid];
#pragma unroll
    for (int t = 0; t < 4; t++) {
        int idx = tid + t * 256;
        int il = idx >> 6, jl = idx & 63;
        const float* pi = &pos[(b * NN + i0 + il) * 3];
        const float* pj = &pos[(b * NN + j0 + jl) * 3];
        float dx = pi[0] - pj[0], dy = pi[1] - pj[1], dz = pi[2] - pj[2];
        float sq = fmaf(dx, dx, fmaf(dy, dy, dz * dz));
        dsm[il][jl] = (sq > 0.0f) ? sqrtfast(sq) : 0.0f;
    }
    __syncthreads();

    int il = tid >> 4;
    int k0 = (tid & 15) * 8;

    ull base2[4], wd2[4], acc2[4];
#pragma unroll
    for (int p = 0; p < 4; p++) {
        float wlo = 0.5f * We1[2 * HH * HH + k0 + 2 * p];
        float whi = 0.5f * We1[2 * HH * HH + k0 + 2 * p + 1];
        wd2[p] = pack2(wlo, whi);
        base2[p] = ((const ull*)&bsm[il][k0])[p];
        acc2[p] = 0ULL;
    }

#pragma unroll 4
    for (int jl = 0; jl < TJE; jl++) {
        float dist = dsm[il][jl];
        float mj = msm[jl];
        ull dist2 = pack2(dist, dist);
        ull mj2 = pack2(mj, mj);
        ulonglong2 qa = *(const ulonglong2*)&qsm[jl][k0];
        ulonglong2 qb = *(const ulonglong2*)&qsm[jl][k0 + 4];
        ull qv[4] = {qa.x, qa.y, qb.x, qb.y};
#pragma unroll
        for (int p = 0; p < 4; p++) {
            ull h2 = fma2(dist2, wd2[p], add2(base2[p], qv[p]));  // h/2
            float hl, hh; unpack2(h2, hl, hh);
            ull t2 = pack2(tanhfast(hl), tanhfast(hh));
            ull s2 = fma2(h2, t2, h2);        // silu(h) = h2*(1+t)
            acc2[p] = fma2(mj2, s2, acc2[p]); // += mj * silu
        }
    }
    float* dst = &g_S[js][(b * NN + i0 + il) * HH + k0];
#pragma unroll
    for (int p = 0; p < 4; p++) {
        float lo, hi; unpack2(acc2[p], lo, hi);
        dst[2 * p] = lo;
        dst[2 * p + 1] = hi;
    }
}

// ---------------------------------------------------------------------------
// Kernel 3: agg -> node MLP -> residual.  8 rows/CTA (4 pairs), 256 threads,
// grid 256 (~2 CTAs/SM). tid: k = tid&127, rh = tid>>7 (pairs 2rh, 2rh+1).
// Packed f32x2 math, reg-double-buffered weights, 3 barriers total.
// ---------------------------------------------------------------------------
__global__ __launch_bounds__(256)
void k_final(const float* __restrict__ node,
             const float* __restrict__ mask,
             const float* __restrict__ We2,
             const float* __restrict__ be2,
             const float* __restrict__ Wn1,
             const float* __restrict__ bn1,
             const float* __restrict__ Wn2,
             const float* __restrict__ bn2,
             float* __restrict__ out) {
    __shared__ __align__(16) ull XA2[2 * HH][4];  // 8 KB: [X|A] packed row-pairs
    __shared__ __align__(16) ull SU2[HH][4];      // 4 KB: S then U
    __shared__ float mrow[8];
    __shared__ float cntsh;

    int row0 = blockIdx.x * 8;
    int b = row0 >> 8;
    int tid = threadIdx.x;
    int k = tid & 127;
    int rh = tid >> 7;                 // pairs 2rh, 2rh+1 (rows 4rh..4rh+3)

#pragma unroll
    for (int t = 0; t < 2; t++) {
        int idx = tid + t * 256;       // 512 entries
        int e = idx >> 2, p = idx & 3;
        int g0 = (row0 + 2 * p) * HH + e;
        int g1 = g0 + HH;
        XA2[e][p] = pack2(node[g0], node[g1]);
        float s0 = 0.0f, s1 = 0.0f;
#pragma unroll
        for (int s = 0; s < NSPLIT; s++) { s0 += g_S[s][g0]; s1 += g_S[s][g1]; }
        SU2[e][p] = pack2(s0, s1);
    }
    if (tid < 8) mrow[tid] = mask[row0 + tid];
    if (tid < 32) {
        float c = 0.0f;
#pragma unroll
        for (int m = 0; m < 8; m++) c += mask[b * NN + tid * 8 + m];
#pragma unroll
        for (int o = 16; o; o >>= 1) c += __shfl_xor_sync(0xffffffffu, c, o);
        if (tid == 0) cntsh = c;
    }
    __syncthreads();
    float cnt = cntsh;

    // Stage A: agg = m*(S@We2 + cnt*be2)/max(m*cnt,1) -> XA2[HH+k][2rh..]
    {
        ull acc2[2] = {0ULL, 0ULL};
        const float* W = We2 + k;
        float w0[16], w1[16];
#pragma unroll
        for (int e = 0; e < 16; e++) w0[e] = W[e * HH];
#pragma unroll
        for (int c = 0; c < 8; c++) {
            float* wc = (c & 1) ? w1 : w0;
            float* wn = (c & 1) ? w0 : w1;
            if (c < 7) {
#pragma unroll
                for (int e = 0; e < 16; e++) wn[e] = W[((c + 1) * 16 + e) * HH];
            }
#pragma unroll
            for (int e = 0; e < 16; e++) {
                ull w2 = pack2(wc[e], wc[e]);
                ulonglong2 sv = *(const ulonglong2*)&SU2[c * 16 + e][2 * rh];
                acc2[0] = fma2(sv.x, w2, acc2[0]);
                acc2[1] = fma2(sv.y, w2, acc2[1]);
            }
        }
        float be2k = be2[k];
#pragma unroll
        for (int pp = 0; pp < 2; pp++) {
            int pr = 2 * rh + pp;
            float lo, hi; unpack2(acc2[pp], lo, hi);
            float m0 = mrow[2 * pr], m1 = mrow[2 * pr + 1];
            float a0 = m0 * (lo + cnt * be2k) / fmaxf(m0 * cnt, 1.0f);
            float a1 = m1 * (hi + cnt * be2k) / fmaxf(m1 * cnt, 1.0f);
            XA2[HH + k][pr] = pack2(a0, a1);
        }
    }
    __syncthreads();

    // Stage B: u1 = silu([X|A] @ Wn1 + bn1) -> SU2
    {
        float b1 = bn1[k];
        ull acc2[2] = {pack2(b1, b1), pack2(b1, b1)};
        const float* W = Wn1 + k;
        float w0[16], w1[16];
#pragma unroll
        for (int e = 0; e < 16; e++) w0[e] = W[e * HH];
#pragma unroll
        for (int c = 0; c < 16; c++) {
            float* wc = (c & 1) ? w1 : w0;
            float* wn = (c & 1) ? w0 : w1;
            if (c < 15) {
#pragma unroll
                for (int e = 0; e < 16; e++) wn[e] = W[((c + 1) * 16 + e) * HH];
            }
#pragma unroll
            for (int e = 0; e < 16; e++) {
                ull w2 = pack2(wc[e], wc[e]);
                ulonglong2 xv = *(const ulonglong2*)&XA2[c * 16 + e][2 * rh];
                acc2[0] = fma2(xv.x, w2, acc2[0]);
                acc2[1] = fma2(xv.y, w2, acc2[1]);
            }
        }
#pragma unroll
        for (int pp = 0; pp < 2; pp++) {
            int pr = 2 * rh + pp;
            float lo, hi; unpack2(acc2[pp], lo, hi);
            float u0 = lo * fast_sigmoid(lo);
            float u1 = hi * fast_sigmoid(hi);
            SU2[k][pr] = pack2(u0, u1);
        }
    }
    __syncthreads();

    // Stage C: out = node + m * (u1 @ Wn2 + bn2)
    {
        float b2 = bn2[k];
        ull acc2[2] = {pack2(b2, b2), pack2(b2, b2)};
        const float* W = Wn2 + k;
        float w0[16], w1[16];
#pragma unroll
        for (int e = 0; e < 16; e++) w0[e] = W[e * HH];
#pragma unroll
        for (int c = 0; c < 8; c++) {
            float* wc = (c & 1) ? w1 : w0;
            float* wn = (c & 1) ? w0 : w1;
            if (c < 7) {
#pragma unroll
                for (int e = 0; e < 16; e++) wn[e] = W[((c + 1) * 16 + e) * HH];
            }
#pragma unroll
            for (int e = 0; e < 16; e++) {
                ull w2 = pack2(wc[e], wc[e]);
                ulonglong2 uv = *(const ulonglong2*)&SU2[c * 16 + e][2 * rh];
                acc2[0] = fma2(uv.x, w2, acc2[0]);
                acc2[1] = fma2(uv.y, w2, acc2[1]);
            }
        }
#pragma unroll
        for (int pp = 0; pp < 2; pp++) {
            int pr = 2 * rh + pp;
            float lo, hi; unpack2(acc2[pp], lo, hi);
            float x0, x1; unpack2(XA2[k][pr], x0, x1);
            out[(row0 + 2 * pr) * HH + k] = x0 + mrow[2 * pr] * lo;
            out[(row0 + 2 * pr + 1) * HH + k] = x1 + mrow[2 * pr + 1] * hi;
        }
    }
}

extern "C" void kernel_launch(void* const* d_in, const int* in_sizes, int n_in,
                              void* d_out, int out_size) {
    (void)in_sizes; (void)n_in; (void)out_size;
    const float* node = (const float*)d_in[0];
    const float* pos  = (const float*)d_in[1];
    const float* mask = (const float*)d_in[2];
    const float* We1  = (const float*)d_in[3];
    const float* be1  = (const float*)d_in[4];
    const float* We2  = (const float*)d_in[5];
    const float* be2  = (const float*)d_in[6];
    const float* Wn1  = (const float*)d_in[7];
    const float* bn1  = (const float*)d_in[8];
    const float* Wn2  = (const float*)d_in[9];
    const float* bn2  = (const float*)d_in[10];
    float* out = (float*)d_out;

    k_pq<<<ROWS / 8, 256>>>(node, We1, be1);
    k_edge<<<dim3(NSPLIT, NN / TI, BB), 256>>>(pos, mask, We1);
    k_final<<<ROWS / 8, 256>>>(node, mask, We2, be2, Wn1, bn1, Wn2, bn2, out);
}

// round 9
// speedup vs baseline: 1.1782x; 1.0821x over previous
#include <cuda_runtime.h>
#include <cuda_bf16.h>

// Problem constants (B=8, N=256, H=128)
#define BB 8
#define NN 256
#define HH 128
#define ROWS (BB * NN)        // 2048
#define TIF 16                // i-rows per fused CTA

typedef unsigned long long ull;

// Scratch (allocation-free rule: __device__ globals)
// g_P = 0.5*(node@We1a + be1); g_Q = 0.5*(node@We1b)  (pre-halved for tanh-silu)
__device__ float g_P[ROWS * HH];
__device__ float g_Q[ROWS * HH];

// ---------------- packed f32x2 + MUFU helpers ----------------
__device__ __forceinline__ ull fma2(ull a, ull b, ull c) {
    ull d; asm("fma.rn.f32x2 %0, %1, %2, %3;" : "=l"(d) : "l"(a), "l"(b), "l"(c)); return d;
}
__device__ __forceinline__ ull add2(ull a, ull b) {
    ull d; asm("add.rn.f32x2 %0, %1, %2;" : "=l"(d) : "l"(a), "l"(b)); return d;
}
__device__ __forceinline__ ull mul2(ull a, ull b) {
    ull d; asm("mul.rn.f32x2 %0, %1, %2;" : "=l"(d) : "l"(a), "l"(b)); return d;
}
__device__ __forceinline__ ull pack2(float lo, float hi) {
    ull d; asm("mov.b64 %0, {%1, %2};" : "=l"(d) : "f"(lo), "f"(hi)); return d;
}
__device__ __forceinline__ void unpack2(ull v, float& lo, float& hi) {
    asm("mov.b64 {%0, %1}, %2;" : "=f"(lo), "=f"(hi) : "l"(v));
}
__device__ __forceinline__ float tanhfast(float x) {
    float y; asm("tanh.approx.f32 %0, %1;" : "=f"(y) : "f"(x)); return y;
}
__device__ __forceinline__ float sqrtfast(float x) {
    float y; asm("sqrt.approx.f32 %0, %1;" : "=f"(y) : "f"(x)); return y;
}
__device__ __forceinline__ float fast_sigmoid(float x) {
    float e; asm("ex2.approx.f32 %0, %1;" : "=f"(e) : "f"(-1.4426950408889634f * x));
    float r; asm("rcp.approx.f32 %0, %1;" : "=f"(r) : "f"(1.0f + e));
    return r;
}

// ---------------------------------------------------------------------------
// Kernel 1: P' = 0.5*(node@We1a + be1) ; Q' = 0.5*(node@We1b)
// grid 128 x 512 thr, 16 rows/CTA. ENTIRE We1[0:256] (128 KB) staged to smem
// once; inner loop is pure LDS + fma2, no global loads.
// tid: k = tid&127, half = bit7 (P vs Q), rg = bit8 (4 row-pairs each).
// ---------------------------------------------------------------------------
#define PQ_SMEM (131072 + 8192)
__global__ __launch_bounds__(512, 1)
void k_pq(const float* __restrict__ node,
          const float* __restrict__ We1,
          const float* __restrict__ be1) {
    extern __shared__ __align__(16) char smem_pq[];
    float* wsm = (float*)smem_pq;                 // [e_glob 0..255][k]  128 KB
    ull*   xs2 = (ull*)(smem_pq + 131072);        // [e][p<8]           8 KB

    int row0 = blockIdx.x * 16;
    int tid = threadIdx.x;
    int k = tid & 127;
    int half = (tid >> 7) & 1;
    int rg = tid >> 8;                            // row-pair group: pairs rg*4..+3

    {   // stage all weights: 8192 float4
        const float4* wsrc = (const float4*)We1;
        float4* wdst = (float4*)wsm;
#pragma unroll
        for (int i = 0; i < 16; i++) wdst[tid + i * 512] = wsrc[tid + i * 512];
    }
    {   // pack x row-pairs: 1024 ull entries
#pragma unroll
        for (int t = 0; t < 2; t++) {
            int idx = tid + t * 512;
            int e = idx & 127, p = idx >> 7;
            xs2[e * 8 + p] = pack2(node[(row0 + 2 * p) * HH + e],
                                   node[(row0 + 2 * p + 1) * HH + e]);
        }
    }
    __syncthreads();

    const float* W = wsm + half * (HH * HH) + k;
    float bv = half ? 0.0f : be1[k];
    ull acc2[4];
#pragma unroll
    for (int p = 0; p < 4; p++) acc2[p] = pack2(bv, bv);

#pragma unroll 8
    for (int e = 0; e < HH; e++) {
        float w = W[e * HH];
        ull w2 = pack2(w, w);
        ulonglong2 xa = *(const ulonglong2*)&xs2[e * 8 + rg * 4];
        ulonglong2 xb = *(const ulonglong2*)&xs2[e * 8 + rg * 4 + 2];
        acc2[0] = fma2(xa.x, w2, acc2[0]);
        acc2[1] = fma2(xa.y, w2, acc2[1]);
        acc2[2] = fma2(xb.x, w2, acc2[2]);
        acc2[3] = fma2(xb.y, w2, acc2[3]);
    }

    float* dst = half ? g_Q : g_P;
    ull hc = pack2(0.5f, 0.5f);
#pragma unroll
    for (int p = 0; p < 4; p++) {
        float lo, hi; unpack2(mul2(acc2[p], hc), lo, hi);
        int pr = rg * 4 + p;
        dst[(row0 + 2 * pr) * HH + k] = lo;
        dst[(row0 + 2 * pr + 1) * HH + k] = hi;
    }
}

// ---------------------------------------------------------------------------
// Fused kernel: edge aggregation (full j-range) + agg scale + node MLP +
// residual. grid (N/TIF, B) = 128 CTAs, 256 threads.
// Main loop: thread = (row-pair ip, k-quad kg); S accumulates packed
// (S[2ip],S[2ip+1]) per k -> written stage-ready to smem.
// Tail: 3 GEMV stages (thread = col k, row-half rh; 4 pairs each).
// ---------------------------------------------------------------------------
#define QSM_OFF  0          // float[256][128]  131072
#define BSM_OFF  131072     // float[16][128]   8192
#define DSM_OFF  139264     // float[16][256]   16384
#define MSM_OFF  155648     // float[256]       1024
#define S2_OFF   156672     // ull[128][8]      8192
#define XA2_OFF  164864     // ull[256][8]      16384
#define SU2_OFF  181248     // ull[128][8]      8192
#define MROW_OFF 189440     // float[16]
#define CNT_OFF  189504     // float
#define FU_SMEM  189568

__global__ __launch_bounds__(256, 1)
void k_fused(const float* __restrict__ node,
             const float* __restrict__ pos,
             const float* __restrict__ mask,
             const float* __restrict__ We1,
             const float* __restrict__ We2,
             const float* __restrict__ be2,
             const float* __restrict__ Wn1,
             const float* __restrict__ bn1,
             const float* __restrict__ Wn2,
             const float* __restrict__ bn2,
             float* __restrict__ out) {
    extern __shared__ __align__(16) char smem[];
    float* QSM  = (float*)(smem + QSM_OFF);
    float* BSM  = (float*)(smem + BSM_OFF);
    float* DSM  = (float*)(smem + DSM_OFF);
    float* MSM  = (float*)(smem + MSM_OFF);
    ull*   S2   = (ull*)(smem + S2_OFF);
    ull*   XA2  = (ull*)(smem + XA2_OFF);
    ull*   SU2  = (ull*)(smem + SU2_OFF);
    float* MROW = (float*)(smem + MROW_OFF);
    float* CNT  = (float*)(smem + CNT_OFF);

    int i0 = blockIdx.x * TIF;
    int b  = blockIdx.y;
    int tid = threadIdx.x;
    int row0 = b * NN + i0;               // global row base for this CTA

    // ---------------- prologue ----------------
    {   // Q for the whole batch row-block: 8192 float4
        const float4* qsrc = (const float4*)&g_Q[b * NN * HH];
#pragma unroll
        for (int i = 0; i < 32; i++)
            ((float4*)QSM)[tid + i * 256] = qsrc[tid + i * 256];
        const float4* bsrc = (const float4*)&g_P[row0 * HH];
#pragma unroll
        for (int i = 0; i < 2; i++)
            ((float4*)BSM)[tid + i * 256] = bsrc[tid + i * 256];
    }
    {   // X row-pairs into XA2[e<128][p]
#pragma unroll
        for (int t = 0; t < 4; t++) {
            int idx = tid + t * 256;
            int e = idx & 127, p = idx >> 7;
            XA2[e * 8 + p] = pack2(node[(row0 + 2 * p) * HH + e],
                                   node[(row0 + 2 * p + 1) * HH + e]);
        }
    }
    {   // dist tile 16 x 256
#pragma unroll
        for (int t = 0; t < 16; t++) {
            int idx = tid + t * 256;
            int r = idx >> 8, jl = idx & 255;
            const float* pi = &pos[(row0 + r) * 3];
            const float* pj = &pos[(b * NN + jl) * 3];
            float dx = pi[0] - pj[0], dy = pi[1] - pj[1], dz = pi[2] - pj[2];
            float sq = fmaf(dx, dx, fmaf(dy, dy, dz * dz));
            DSM[r * 256 + jl] = (sq > 0.0f) ? sqrtfast(sq) : 0.0f;
        }
    }
    MSM[tid] = mask[b * NN + tid];
    if (tid < 16) MROW[tid] = mask[row0 + tid];
    if (tid < 32) {
        float c = 0.0f;
#pragma unroll
        for (int m = 0; m < 8; m++) c += mask[b * NN + tid * 8 + m];
#pragma unroll
        for (int o = 16; o; o >>= 1) c += __shfl_xor_sync(0xffffffffu, c, o);
        if (tid == 0) *CNT = c;
    }
    __syncthreads();

    // ---------------- main edge loop ----------------
    {
        int kg = tid & 31;                // k-quad: k0..k0+3
        int ip = tid >> 5;                // row-pair 0..7 (rows 2ip, 2ip+1)
        int k0 = kg * 4;

        ull wd2[4], base2[4], acc2[4];
#pragma unroll
        for (int d = 0; d < 4; d++) {
            float w = 0.5f * We1[2 * HH * HH + k0 + d];
            wd2[d] = pack2(w, w);
            base2[d] = pack2(BSM[(2 * ip) * HH + k0 + d],
                             BSM[(2 * ip + 1) * HH + k0 + d]);
            acc2[d] = 0ULL;
        }
        const float* drow0 = &DSM[(2 * ip) * 256];
        const float* drow1 = &DSM[(2 * ip + 1) * 256];

#pragma unroll 4
        for (int jl = 0; jl < NN; jl++) {
            ull dist2 = pack2(drow0[jl], drow1[jl]);
            float m = MSM[jl];
            ull mj2 = pack2(m, m);
            float4 q = *(const float4*)&QSM[jl * HH + k0];
            ull qv[4] = {pack2(q.x, q.x), pack2(q.y, q.y),
                         pack2(q.z, q.z), pack2(q.w, q.w)};
#pragma unroll
            for (int d = 0; d < 4; d++) {
                ull h2 = fma2(dist2, wd2[d], add2(base2[d], qv[d]));  // h/2
                float hl, hh; unpack2(h2, hl, hh);
                ull t2 = pack2(tanhfast(hl), tanhfast(hh));
                ull s2 = fma2(h2, t2, h2);        // silu(h) = h2*(1+t)
                acc2[d] = fma2(mj2, s2, acc2[d]); // += mj * silu
            }
        }
        // stage-ready packed store: S2[e][ip] = (S[2ip][e], S[2ip+1][e])
#pragma unroll
        for (int d = 0; d < 4; d++) S2[(k0 + d) * 8 + ip] = acc2[d];
    }
    __syncthreads();

    // ---------------- tail: 3 GEMV stages ----------------
    int k = tid & 127;
    int rh = tid >> 7;                    // pairs rh*4 .. rh*4+3
    float cnt = *CNT;

    // Stage A: agg = m*(S@We2 + cnt*be2)/max(m*cnt,1) -> XA2[HH+k][pr]
    {
        ull acc2[4] = {0ULL, 0ULL, 0ULL, 0ULL};
        const float* W = We2 + k;
        float w0[16], w1[16];
#pragma unroll
        for (int e = 0; e < 16; e++) w0[e] = W[e * HH];
#pragma unroll
        for (int c = 0; c < 8; c++) {
            float* wc = (c & 1) ? w1 : w0;
            float* wn = (c & 1) ? w0 : w1;
            if (c < 7) {
#pragma unroll
                for (int e = 0; e < 16; e++) wn[e] = W[((c + 1) * 16 + e) * HH];
            }
#pragma unroll
            for (int e = 0; e < 16; e++) {
                ull w2 = pack2(wc[e], wc[e]);
#pragma unroll
                for (int pp = 0; pp < 4; pp++) {
                    ull sv = S2[(c * 16 + e) * 8 + rh * 4 + pp];
                    acc2[pp] = fma2(sv, w2, acc2[pp]);
                }
            }
        }
        float be2k = be2[k];
#pragma unroll
        for (int pp = 0; pp < 4; pp++) {
            int pr = rh * 4 + pp;
            float lo, hi; unpack2(acc2[pp], lo, hi);
            float m0 = MROW[2 * pr], m1 = MROW[2 * pr + 1];
            float a0 = m0 * (lo + cnt * be2k) / fmaxf(m0 * cnt, 1.0f);
            float a1 = m1 * (hi + cnt * be2k) / fmaxf(m1 * cnt, 1.0f);
            XA2[(HH + k) * 8 + pr] = pack2(a0, a1);
        }
    }
    __syncthreads();

    // Stage B: u1 = silu([X|A] @ Wn1 + bn1) -> SU2
    {
        float b1 = bn1[k];
        ull acc2[4];
#pragma unroll
        for (int pp = 0; pp < 4; pp++) acc2[pp] = pack2(b1, b1);
        const float* W = Wn1 + k;
        float w0[16], w1[16];
#pragma unroll
        for (int e = 0; e < 16; e++) w0[e] = W[e * HH];
#pragma unroll
        for (int c = 0; c < 16; c++) {
            float* wc = (c & 1) ? w1 : w0;
            float* wn = (c & 1) ? w0 : w1;
            if (c < 15) {
#pragma unroll
                for (int e = 0; e < 16; e++) wn[e] = W[((c + 1) * 16 + e) * HH];
            }
#pragma unroll
            for (int e = 0; e < 16; e++) {
                ull w2 = pack2(wc[e], wc[e]);
#pragma unroll
                for (int pp = 0; pp < 4; pp++) {
                    ull xv = XA2[(c * 16 + e) * 8 + rh * 4 + pp];
                    acc2[pp] = fma2(xv, w2, acc2[pp]);
                }
            }
        }
#pragma unroll
        for (int pp = 0; pp < 4; pp++) {
            int pr = rh * 4 + pp;
            float lo, hi; unpack2(acc2[pp], lo, hi);
            SU2[k * 8 + pr] = pack2(lo * fast_sigmoid(lo), hi * fast_sigmoid(hi));
        }
    }
    __syncthreads();

    // Stage C: out = node + m * (u1 @ Wn2 + bn2)
    {
        float b2 = bn2[k];
        ull acc2[4];
#pragma unroll
        for (int pp = 0; pp < 4; pp++) acc2[pp] = pack2(b2, b2);
        const float* W = Wn2 + k;
        float w0[16], w1[16];
#pragma unroll
        for (int e = 0; e < 16; e++) w0[e] = W[e * HH];
#pragma unroll
        for (int c = 0; c < 8; c++) {
            float* wc = (c & 1) ? w1 : w0;
            float* wn = (c & 1) ? w0 : w1;
            if (c < 7) {
#pragma unroll
                for (int e = 0; e < 16; e++) wn[e] = W[((c + 1) * 16 + e) * HH];
            }
#pragma unroll
            for (int e = 0; e < 16; e++) {
                ull w2 = pack2(wc[e], wc[e]);
#pragma unroll
                for (int pp = 0; pp < 4; pp++) {
                    ull uv = SU2[(c * 16 + e) * 8 + rh * 4 + pp];
                    acc2[pp] = fma2(uv, w2, acc2[pp]);
                }
            }
        }
#pragma unroll
        for (int pp = 0; pp < 4; pp++) {
            int pr = rh * 4 + pp;
            float lo, hi; unpack2(acc2[pp], lo, hi);
            float x0, x1; unpack2(XA2[k * 8 + pr], x0, x1);
            out[(row0 + 2 * pr) * HH + k] = x0 + MROW[2 * pr] * lo;
            out[(row0 + 2 * pr + 1) * HH + k] = x1 + MROW[2 * pr + 1] * hi;
        }
    }
}

extern "C" void kernel_launch(void* const* d_in, const int* in_sizes, int n_in,
                              void* d_out, int out_size) {
    (void)in_sizes; (void)n_in; (void)out_size;
    const float* node = (const float*)d_in[0];
    const float* pos  = (const float*)d_in[1];
    const float* mask = (const float*)d_in[2];
    const float* We1  = (const float*)d_in[3];
    const float* be1  = (const float*)d_in[4];
    const float* We2  = (const float*)d_in[5];
    const float* be2  = (const float*)d_in[6];
    const float* Wn1  = (const float*)d_in[7];
    const float* bn1  = (const float*)d_in[8];
    const float* Wn2  = (const float*)d_in[9];
    const float* bn2  = (const float*)d_in[10];
    float* out = (float*)d_out;

    cudaFuncSetAttribute(k_pq, cudaFuncAttributeMaxDynamicSharedMemorySize, PQ_SMEM);
    cudaFuncSetAttribute(k_fused, cudaFuncAttributeMaxDynamicSharedMemorySize, FU_SMEM);

    k_pq<<<ROWS / 16, 512, PQ_SMEM>>>(node, We1, be1);
    k_fused<<<dim3(NN / TIF, BB), 256, FU_SMEM>>>(node, pos, mask, We1, We2, be2,
                                                  Wn1, bn1, Wn2, bn2, out);
}